// round 7
// baseline (speedup 1.0000x reference)
#include <cuda_runtime.h>

constexpr int PB = 2, PC = 64, PH = 256, PW = 256, IMG = 512;

// Scratch (device globals)
__device__ float g_R[PB * 3 * PH * PW];   // resized img (3 ch)
__device__ float g_S[PB * PH * PW];       // inp . w_comp
__device__ float g_PXo[32 * PW];          // pos basis [o][w]
__device__ float g_PYo[32 * PH];
__device__ float g_T1t[PH * PW];          // T1t[h][w] = sum_o PX[o,w]*PY[o,h]
__device__ float g_GX[3 * PW];            // GX[d][w] = sum_o PX[o,clamp(w+2(d-1))]*PX[o,w]
__device__ float g_GY[3 * PH];
__device__ float g_M[9];                  // w_img^T w_img
__device__ float g_phi[PB * 9 * PH * PW]; // per-neighbor weight, 4.7 MB

// ---------------------------------------------------------------------------
// K1: prep = pos basis (blocks 0..63) + S map (64..575) + resize (576..2111)
// ---------------------------------------------------------------------------
__device__ __forceinline__ void make_taps(int o, int* j, float* wt) {
    j[0] = 2 * o - 1; j[1] = 2 * o; j[2] = 2 * o + 1; j[3] = 2 * o + 2;
    wt[0] = 0.125f; wt[1] = 0.375f; wt[2] = 0.375f; wt[3] = 0.125f;
    if (o == 0) {
        j[0] = 0; wt[0] = 0.f;
        wt[1] = 3.f / 7.f; wt[2] = 3.f / 7.f; wt[3] = 1.f / 7.f;
    } else if (o == 255) {
        j[3] = 511; wt[3] = 0.f;
        wt[0] = 1.f / 7.f; wt[1] = 3.f / 7.f; wt[2] = 3.f / 7.f;
    }
}

__global__ __launch_bounds__(256) void prep_kernel(
    const float* __restrict__ inp, const float* __restrict__ img,
    const float* __restrict__ wp, const float* __restrict__ w_comp)
{
    int bx = blockIdx.x;
    if (bx < 64) {
        // ---- positional basis ----
        int o = bx >> 1;
        int half = bx & 1;
        int p = threadIdx.x;
        const float kexp = -0.28782313662425575f;  // -ln(10000)/32
        float acc = 0.f;
        int cbase = half ? 32 : 0;
#pragma unroll
        for (int i = 0; i < 16; i++) {
            float dv = __expf((float)(2 * i) * kexp);
            float s, c;
            __sincosf((float)p * dv, &s, &c);
            acc += wp[o * 64 + cbase + 2 * i] * s + wp[o * 64 + cbase + 2 * i + 1] * c;
        }
        if (half == 0) g_PXo[o * 256 + p] = acc;
        else           g_PYo[o * 256 + p] = acc;
    } else if (bx < 576) {
        // ---- S = inp . w_comp ----
        int idx = (bx - 64) * 256 + threadIdx.x;
        int b = idx >> 16;
        int pix = idx & 65535;
        const float* ip = inp + ((b * PC) << 16) + pix;
        float acc = 0.f;
#pragma unroll
        for (int c = 0; c < PC; c++)
            acc += __ldg(&w_comp[c]) * __ldg(&ip[c << 16]);
        g_S[(b << 16) + pix] = acc;
    } else {
        // ---- bilinear resize 512->256 (antialias) ----
        int bb = bx - 576;
        int h = bb & 255;
        int bc = bb >> 8;
        int w = threadIdx.x;
        int jh[4], jw[4]; float wh[4], ww[4];
        make_taps(h, jh, wh);
        make_taps(w, jw, ww);
        const float* ip = img + bc * IMG * IMG;
        float acc = 0.f;
#pragma unroll
        for (int a = 0; a < 4; a++) {
            float row = 0.f;
#pragma unroll
            for (int t = 0; t < 4; t++) row += ww[t] * __ldg(&ip[jh[a] * IMG + jw[t]]);
            acc += wh[a] * row;
        }
        g_R[(bc * 256 + h) * 256 + w] = acc;
    }
}

// ---------------------------------------------------------------------------
// K2: gram tables
// ---------------------------------------------------------------------------
__global__ void tables_kernel(const float* __restrict__ w_img) {
    int bx = blockIdx.x, t = threadIdx.x;
    if (bx < 256) {
        __shared__ float sPY[32];
        if (t < 32) sPY[t] = g_PYo[t * 256 + bx];
        __syncthreads();
        float a = 0.f;
#pragma unroll
        for (int o = 0; o < 32; o++) a += sPY[o] * g_PXo[o * 256 + t];
        g_T1t[bx * 256 + t] = a;
    } else {
#pragma unroll
        for (int d = 0; d < 3; d++) {
            int q = min(max(t + 2 * (d - 1), 0), 255);
            float ax = 0.f, ay = 0.f;
#pragma unroll
            for (int o = 0; o < 32; o++) {
                ax += g_PXo[o * 256 + q] * g_PXo[o * 256 + t];
                ay += g_PYo[o * 256 + q] * g_PYo[o * 256 + t];
            }
            g_GX[d * 256 + t] = ax;
            g_GY[d * 256 + t] = ay;
        }
        if (t < 9) {
            int i = t / 3, j = t % 3;
            float a = 0.f;
#pragma unroll
            for (int o = 0; o < 32; o++) a += w_img[o * 3 + i] * w_img[o * 3 + j];
            g_M[t] = a;
        }
    }
}

// ---------------------------------------------------------------------------
// K3: phi kernel — one thread per pixel, 9-neighbor loop (amortized center).
//   OOB neighbors produce finite garbage; agg's zero inp-halo kills them.
// ---------------------------------------------------------------------------
__global__ __launch_bounds__(256) void phi_kernel() {
    int idx = blockIdx.x * 256 + threadIdx.x;   // 0..131071
    int b = idx >> 16;
    int h = (idx >> 8) & 255;
    int w = idx & 255;

    const float* Rb = g_R + ((b * 3) << 16);
    const float* Sb = g_S + (b << 16);
    const int ctr = (h << 8) + w;

    float r0 = __ldg(&Rb[ctr]);
    float r1 = __ldg(&Rb[65536 + ctr]);
    float r2 = __ldg(&Rb[131072 + ctr]);
    float mc0 = __ldg(&g_M[0]) * r0 + __ldg(&g_M[1]) * r1 + __ldg(&g_M[2]) * r2;
    float mc1 = __ldg(&g_M[3]) * r0 + __ldg(&g_M[4]) * r1 + __ldg(&g_M[5]) * r2;
    float mc2 = __ldg(&g_M[6]) * r0 + __ldg(&g_M[7]) * r1 + __ldg(&g_M[8]) * r2;

#pragma unroll
    for (int k = 0; k < 9; k++) {
        int di = (k / 3), dj = (k % 3);
        int hn = min(max(h + 2 * di - 2, 0), 255);
        int wn = min(max(w + 2 * dj - 2, 0), 255);
        int nb = (hn << 8) + wn;
        float fs = __ldg(&Rb[nb]) * mc0 + __ldg(&Rb[65536 + nb]) * mc1
                 + __ldg(&Rb[131072 + nb]) * mc2;
        fs += __ldg(&g_GX[dj * 256 + w]) + __ldg(&g_GY[di * 256 + h]);
        fs += __ldg(&g_T1t[(h << 8) + wn]) + __ldg(&g_T1t[(hn << 8) + w]);
        float s = __ldg(&Sb[nb]);
        g_phi[(((b * 9 + k) << 16)) + ctr] = fs * (1.f / (1.f + __expf(-s)));
    }
}

// ---------------------------------------------------------------------------
// K4: aggregation.  Tile 32(w) x 8(h), smem 36 x 12 rows, 16 ch per block.
//   grid (8, 32, 8): z = b*4 + chgroup.  ONE __syncthreads per block.
//   All 32 lanes productive; row stride 36 keeps LDS conflict-free.
// ---------------------------------------------------------------------------
constexpr int TW = 32, TH = 8;
constexpr int SW = 36, SH = 12;
constexpr int CCH = 16;

__global__ __launch_bounds__(256) void agg_kernel(
    const float* __restrict__ inp, float* __restrict__ out)
{
    const int z  = blockIdx.z;
    const int b  = z >> 2;
    const int ch0 = (z & 3) * CCH;
    const int h0 = blockIdx.y * TH;
    const int w0 = blockIdx.x * TW;
    const int tid = threadIdx.x;
    const int tx = tid & 31;
    const int ty = tid >> 5;      // 0..7

    __shared__ float sT[CCH][SH][SW];

    // main columns (0..31)
    const int gw = w0 - 2 + tx;
    const bool vw = (unsigned)gw < (unsigned)PW;
    const int gh0 = h0 - 2 + ty;
    const int gh1 = gh0 + 8;
    const bool vh0 = (unsigned)gh0 < (unsigned)PH;
    const bool vh1 = (unsigned)gh1 < (unsigned)PH;
    // extra columns (32..35), loaded by tx<4
    const int gwE = w0 + 30 + tx;
    const bool vwE = (tx < 4) && (gwE < PW);

    const int h = h0 + ty, w = w0 + tx;
    const int ctr = (h << 8) + w;

    // ---- phi loads ----
    float phi[9];
    {
        const float* pb = g_phi + ((b * 9) << 16) + ctr;
#pragma unroll
        for (int k = 0; k < 9; k++) phi[k] = __ldg(&pb[k << 16]);
    }

    // ---- issue inp loads, stage to smem ----
    const int ibase = ((b * PC + ch0) << 16);
#pragma unroll
    for (int c = 0; c < CCH; c++) {
        const int cofs = ibase + (c << 16);
        sT[c][ty][tx]     = (vw && vh0) ? __ldg(&inp[cofs + (gh0 << 8) + gw]) : 0.f;
        if (ty < 4)
            sT[c][ty + 8][tx] = (vw && vh1) ? __ldg(&inp[cofs + (gh1 << 8) + gw]) : 0.f;
        // extra 4 columns: tx<4 covers rows ty and ty+8 (ty<4)
        if (tx < 4) {
            sT[c][ty][32 + tx]     = (vwE && vh0) ? __ldg(&inp[cofs + (gh0 << 8) + gwE]) : 0.f;
            if (ty < 4)
                sT[c][ty + 8][32 + tx] = (vwE && vh1) ? __ldg(&inp[cofs + (gh1 << 8) + gwE]) : 0.f;
        }
    }
    __syncthreads();

    // ---- compute ----
    const int obase = ((b * PC + ch0) << 16) + ctr;
#pragma unroll
    for (int c = 0; c < CCH; c++) {
        float acc = 0.f;
#pragma unroll
        for (int k = 0; k < 9; k++)
            acc += phi[k] * sT[c][ty + 2 * (k / 3)][tx + 2 * (k % 3)];
        out[obase + (c << 16)] = acc;
    }
}

// ---------------------------------------------------------------------------
extern "C" void kernel_launch(void* const* d_in, const int* in_sizes, int n_in,
                              void* d_out, int out_size)
{
    const float* inp    = (const float*)d_in[0];   // [2,64,256,256]
    const float* img    = (const float*)d_in[1];   // [2,3,512,512]
    const float* w_pos  = (const float*)d_in[2];   // [32,64]
    const float* w_img  = (const float*)d_in[3];   // [32,3]
    const float* w_comp = (const float*)d_in[4];   // [64]
    float* out = (float*)d_out;

    prep_kernel<<<2112, 256>>>(inp, img, w_pos, w_comp);
    tables_kernel<<<257, 256>>>(w_img);
    phi_kernel<<<512, 256>>>();
    dim3 grid(PW / TW, PH / TH, PB * 4);   // 8 x 32 x 8 = 2048
    agg_kernel<<<grid, 256>>>(inp, out);
}

// round 8
// speedup vs baseline: 1.3692x; 1.3692x over previous
#include <cuda_runtime.h>

constexpr int PB = 2, PC = 64, PH = 256, PW = 256, IMG = 512;

// Scratch (device globals)
__device__ float g_R[PB * 3 * PH * PW];   // resized img (3 ch)
__device__ float g_S[PB * PH * PW];       // inp . w_comp
__device__ float g_PXo[32 * PW];          // pos basis [o][w]
__device__ float g_PYo[32 * PH];
__device__ float g_T1t[PH * PW];          // T1t[h][w] = sum_o PX[o,w]*PY[o,h]
__device__ float g_GX[3 * PW];            // GX[d][w] = sum_o PX[o,clamp(w+2(d-1))]*PX[o,w]
__device__ float g_GY[3 * PH];
__device__ float g_M[9];                  // w_img^T w_img
__device__ float g_phi[PB * 9 * PH * PW]; // per-neighbor weight, 4.7 MB

// ---------------------------------------------------------------------------
// K1: prep = pos basis (blocks 0..63) + S map (64..575) + resize (576..2111)
// ---------------------------------------------------------------------------
__device__ __forceinline__ void make_taps(int o, int* j, float* wt) {
    j[0] = 2 * o - 1; j[1] = 2 * o; j[2] = 2 * o + 1; j[3] = 2 * o + 2;
    wt[0] = 0.125f; wt[1] = 0.375f; wt[2] = 0.375f; wt[3] = 0.125f;
    if (o == 0) {
        j[0] = 0; wt[0] = 0.f;
        wt[1] = 3.f / 7.f; wt[2] = 3.f / 7.f; wt[3] = 1.f / 7.f;
    } else if (o == 255) {
        j[3] = 511; wt[3] = 0.f;
        wt[0] = 1.f / 7.f; wt[1] = 3.f / 7.f; wt[2] = 3.f / 7.f;
    }
}

__global__ __launch_bounds__(256) void prep_kernel(
    const float* __restrict__ inp, const float* __restrict__ img,
    const float* __restrict__ wp, const float* __restrict__ w_comp)
{
    int bx = blockIdx.x;
    if (bx < 64) {
        // ---- positional basis ----
        int o = bx >> 1;
        int half = bx & 1;
        int p = threadIdx.x;
        const float kexp = -0.28782313662425575f;  // -ln(10000)/32
        float acc = 0.f;
        int cbase = half ? 32 : 0;
#pragma unroll
        for (int i = 0; i < 16; i++) {
            float dv = __expf((float)(2 * i) * kexp);
            float s, c;
            __sincosf((float)p * dv, &s, &c);
            acc += wp[o * 64 + cbase + 2 * i] * s + wp[o * 64 + cbase + 2 * i + 1] * c;
        }
        if (half == 0) g_PXo[o * 256 + p] = acc;
        else           g_PYo[o * 256 + p] = acc;
    } else if (bx < 576) {
        // ---- S = inp . w_comp ----
        int idx = (bx - 64) * 256 + threadIdx.x;
        int b = idx >> 16;
        int pix = idx & 65535;
        const float* ip = inp + ((b * PC) << 16) + pix;
        float acc = 0.f;
#pragma unroll
        for (int c = 0; c < PC; c++)
            acc += __ldg(&w_comp[c]) * __ldg(&ip[c << 16]);
        g_S[(b << 16) + pix] = acc;
    } else {
        // ---- bilinear resize 512->256 (antialias) ----
        int bb = bx - 576;
        int h = bb & 255;
        int bc = bb >> 8;
        int w = threadIdx.x;
        int jh[4], jw[4]; float wh[4], ww[4];
        make_taps(h, jh, wh);
        make_taps(w, jw, ww);
        const float* ip = img + bc * IMG * IMG;
        float acc = 0.f;
#pragma unroll
        for (int a = 0; a < 4; a++) {
            float row = 0.f;
#pragma unroll
            for (int t = 0; t < 4; t++) row += ww[t] * __ldg(&ip[jh[a] * IMG + jw[t]]);
            acc += wh[a] * row;
        }
        g_R[(bc * 256 + h) * 256 + w] = acc;
    }
}

// ---------------------------------------------------------------------------
// K2: gram tables
// ---------------------------------------------------------------------------
__global__ void tables_kernel(const float* __restrict__ w_img) {
    int bx = blockIdx.x, t = threadIdx.x;
    if (bx < 256) {
        __shared__ float sPY[32];
        if (t < 32) sPY[t] = g_PYo[t * 256 + bx];
        __syncthreads();
        float a = 0.f;
#pragma unroll
        for (int o = 0; o < 32; o++) a += sPY[o] * g_PXo[o * 256 + t];
        g_T1t[bx * 256 + t] = a;
    } else {
#pragma unroll
        for (int d = 0; d < 3; d++) {
            int q = min(max(t + 2 * (d - 1), 0), 255);
            float ax = 0.f, ay = 0.f;
#pragma unroll
            for (int o = 0; o < 32; o++) {
                ax += g_PXo[o * 256 + q] * g_PXo[o * 256 + t];
                ay += g_PYo[o * 256 + q] * g_PYo[o * 256 + t];
            }
            g_GX[d * 256 + t] = ax;
            g_GY[d * 256 + t] = ay;
        }
        if (t < 9) {
            int i = t / 3, j = t % 3;
            float a = 0.f;
#pragma unroll
            for (int o = 0; o < 32; o++) a += w_img[o * 3 + i] * w_img[o * 3 + j];
            g_M[t] = a;
        }
    }
}

// ---------------------------------------------------------------------------
// K3: phi kernel — one thread per pixel, 9-neighbor loop (amortized center).
//   OOB neighbors produce finite garbage; agg's zero inp-halo kills them.
// ---------------------------------------------------------------------------
__global__ __launch_bounds__(256) void phi_kernel() {
    int idx = blockIdx.x * 256 + threadIdx.x;   // 0..131071
    int b = idx >> 16;
    int h = (idx >> 8) & 255;
    int w = idx & 255;

    const float* Rb = g_R + ((b * 3) << 16);
    const float* Sb = g_S + (b << 16);
    const int ctr = (h << 8) + w;

    float r0 = __ldg(&Rb[ctr]);
    float r1 = __ldg(&Rb[65536 + ctr]);
    float r2 = __ldg(&Rb[131072 + ctr]);
    float mc0 = __ldg(&g_M[0]) * r0 + __ldg(&g_M[1]) * r1 + __ldg(&g_M[2]) * r2;
    float mc1 = __ldg(&g_M[3]) * r0 + __ldg(&g_M[4]) * r1 + __ldg(&g_M[5]) * r2;
    float mc2 = __ldg(&g_M[6]) * r0 + __ldg(&g_M[7]) * r1 + __ldg(&g_M[8]) * r2;

#pragma unroll
    for (int k = 0; k < 9; k++) {
        int di = (k / 3), dj = (k % 3);
        int hn = min(max(h + 2 * di - 2, 0), 255);
        int wn = min(max(w + 2 * dj - 2, 0), 255);
        int nb = (hn << 8) + wn;
        float fs = __ldg(&Rb[nb]) * mc0 + __ldg(&Rb[65536 + nb]) * mc1
                 + __ldg(&Rb[131072 + nb]) * mc2;
        fs += __ldg(&g_GX[dj * 256 + w]) + __ldg(&g_GY[di * 256 + h]);
        fs += __ldg(&g_T1t[(h << 8) + wn]) + __ldg(&g_T1t[(hn << 8) + w]);
        float s = __ldg(&Sb[nb]);
        g_phi[(((b * 9 + k) << 16)) + ctr] = fs * (1.f / (1.f + __expf(-s)));
    }
}

// ---------------------------------------------------------------------------
// K4: aggregation (exact R5 form).  Tile 28(w) x 8(h), smem 32 x 12,
//   16 channels per block (4-way split).  grid (10, 32, 8).
//   Register-buffered load batch, ONE __syncthreads per block.
// ---------------------------------------------------------------------------
constexpr int TW = 28, TH = 8;
constexpr int SW = 32, SH = 12;
constexpr int CCH = 16;

__global__ __launch_bounds__(256) void agg_kernel(
    const float* __restrict__ inp, float* __restrict__ out)
{
    const int z  = blockIdx.z;
    const int b  = z >> 2;
    const int ch0 = (z & 3) * CCH;
    const int h0 = blockIdx.y * TH;
    const int w0 = blockIdx.x * TW;
    const int tid = threadIdx.x;
    const int tx = tid & 31;
    const int ty = tid >> 5;      // 0..7

    __shared__ float sT[CCH][SH][SW];

    const int gw = w0 - 2 + tx;
    const bool vw = (unsigned)gw < (unsigned)PW;
    const int gh0 = h0 - 2 + ty;
    const int gh1 = gh0 + 8;
    const bool vh0 = (unsigned)gh0 < (unsigned)PH;
    const bool vh1 = (unsigned)gh1 < (unsigned)PH;

    const bool active = (tx < TW) && (w0 + tx < PW);
    const int h = h0 + ty, w = w0 + tx;
    const int ctr = (h << 8) + w;

    // ---- issue all global loads up front ----
    float v0[CCH], v1[CCH];
    const int ibase = ((b * PC + ch0) << 16);
#pragma unroll
    for (int c = 0; c < CCH; c++) {
        int cofs = ibase + (c << 16);
        v0[c] = (vw && vh0) ? __ldg(&inp[cofs + (gh0 << 8) + gw]) : 0.f;
        if (ty < 4)
            v1[c] = (vw && vh1) ? __ldg(&inp[cofs + (gh1 << 8) + gw]) : 0.f;
    }
    float phi[9];
    if (active) {
        const float* pb = g_phi + ((b * 9) << 16) + ctr;
#pragma unroll
        for (int k = 0; k < 9; k++) phi[k] = __ldg(&pb[k << 16]);
    }

    // ---- stage to smem ----
#pragma unroll
    for (int c = 0; c < CCH; c++) {
        sT[c][ty][tx] = v0[c];
        if (ty < 4) sT[c][ty + 8][tx] = v1[c];
    }
    __syncthreads();

    // ---- compute ----
    if (active) {
        const int obase = ((b * PC + ch0) << 16) + ctr;
#pragma unroll
        for (int c = 0; c < CCH; c++) {
            float acc = 0.f;
#pragma unroll
            for (int k = 0; k < 9; k++)
                acc += phi[k] * sT[c][ty + 2 * (k / 3)][tx + 2 * (k % 3)];
            out[obase + (c << 16)] = acc;
        }
    }
}

// ---------------------------------------------------------------------------
extern "C" void kernel_launch(void* const* d_in, const int* in_sizes, int n_in,
                              void* d_out, int out_size)
{
    const float* inp    = (const float*)d_in[0];   // [2,64,256,256]
    const float* img    = (const float*)d_in[1];   // [2,3,512,512]
    const float* w_pos  = (const float*)d_in[2];   // [32,64]
    const float* w_img  = (const float*)d_in[3];   // [32,3]
    const float* w_comp = (const float*)d_in[4];   // [64]
    float* out = (float*)d_out;

    prep_kernel<<<2112, 256>>>(inp, img, w_pos, w_comp);
    tables_kernel<<<257, 256>>>(w_img);
    phi_kernel<<<512, 256>>>();
    dim3 grid((PW + TW - 1) / TW, PH / TH, PB * 4);   // 10 x 32 x 8 = 2560
    agg_kernel<<<grid, 256>>>(inp, out);
}

// round 9
// speedup vs baseline: 1.4384x; 1.0505x over previous
#include <cuda_runtime.h>

constexpr int PB = 2, PC = 64, PH = 256, PW = 256, IMG = 512;

// Scratch (device globals)
__device__ float g_R[PB * 3 * PH * PW];   // resized img (3 ch)
__device__ float g_S[PB * PH * PW];       // sigmoid(inp . w_comp)
__device__ float g_PXo[32 * PW];          // pos basis [o][w]
__device__ float g_PYo[32 * PH];
__device__ float g_T1t[PH * PW];          // T1t[h][w] = sum_o PX[o,w]*PY[o,h]
__device__ float g_GX[3 * PW];            // GX[d][w] = sum_o PX[o,clamp(w+2(d-1))]*PX[o,w]
__device__ float g_GY[3 * PH];
__device__ float g_M[9];                  // w_img^T w_img
__device__ float g_phi[PB * 9 * PH * PW]; // per-neighbor weight, 4.7 MB

// ---------------------------------------------------------------------------
// K1: prep = pos basis (blocks 0..63) + sigmoid(S) map (64..575) + resize (576..2111)
// ---------------------------------------------------------------------------
__device__ __forceinline__ void make_taps(int o, int* j, float* wt) {
    j[0] = 2 * o - 1; j[1] = 2 * o; j[2] = 2 * o + 1; j[3] = 2 * o + 2;
    wt[0] = 0.125f; wt[1] = 0.375f; wt[2] = 0.375f; wt[3] = 0.125f;
    if (o == 0) {
        j[0] = 0; wt[0] = 0.f;
        wt[1] = 3.f / 7.f; wt[2] = 3.f / 7.f; wt[3] = 1.f / 7.f;
    } else if (o == 255) {
        j[3] = 511; wt[3] = 0.f;
        wt[0] = 1.f / 7.f; wt[1] = 3.f / 7.f; wt[2] = 3.f / 7.f;
    }
}

__global__ __launch_bounds__(256) void prep_kernel(
    const float* __restrict__ inp, const float* __restrict__ img,
    const float* __restrict__ wp, const float* __restrict__ w_comp)
{
    int bx = blockIdx.x;
    if (bx < 64) {
        // ---- positional basis ----
        int o = bx >> 1;
        int half = bx & 1;
        int p = threadIdx.x;
        const float kexp = -0.28782313662425575f;  // -ln(10000)/32
        float acc = 0.f;
        int cbase = half ? 32 : 0;
#pragma unroll
        for (int i = 0; i < 16; i++) {
            float dv = __expf((float)(2 * i) * kexp);
            float s, c;
            __sincosf((float)p * dv, &s, &c);
            acc += wp[o * 64 + cbase + 2 * i] * s + wp[o * 64 + cbase + 2 * i + 1] * c;
        }
        if (half == 0) g_PXo[o * 256 + p] = acc;
        else           g_PYo[o * 256 + p] = acc;
    } else if (bx < 576) {
        // ---- sigmoid(inp . w_comp) ----
        int idx = (bx - 64) * 256 + threadIdx.x;
        int b = idx >> 16;
        int pix = idx & 65535;
        const float* ip = inp + ((b * PC) << 16) + pix;
        float acc = 0.f;
#pragma unroll
        for (int c = 0; c < PC; c++)
            acc += __ldg(&w_comp[c]) * __ldg(&ip[c << 16]);
        g_S[(b << 16) + pix] = 1.f / (1.f + __expf(-acc));
    } else {
        // ---- bilinear resize 512->256 (antialias) ----
        int bb = bx - 576;
        int h = bb & 255;
        int bc = bb >> 8;
        int w = threadIdx.x;
        int jh[4], jw[4]; float wh[4], ww[4];
        make_taps(h, jh, wh);
        make_taps(w, jw, ww);
        const float* ip = img + bc * IMG * IMG;
        float acc = 0.f;
#pragma unroll
        for (int a = 0; a < 4; a++) {
            float row = 0.f;
#pragma unroll
            for (int t = 0; t < 4; t++) row += ww[t] * __ldg(&ip[jh[a] * IMG + jw[t]]);
            acc += wh[a] * row;
        }
        g_R[(bc * 256 + h) * 256 + w] = acc;
    }
}

// ---------------------------------------------------------------------------
// K2: gram tables
// ---------------------------------------------------------------------------
__global__ void tables_kernel(const float* __restrict__ w_img) {
    int bx = blockIdx.x, t = threadIdx.x;
    if (bx < 256) {
        __shared__ float sPY[32];
        if (t < 32) sPY[t] = g_PYo[t * 256 + bx];
        __syncthreads();
        float a = 0.f;
#pragma unroll
        for (int o = 0; o < 32; o++) a += sPY[o] * g_PXo[o * 256 + t];
        g_T1t[bx * 256 + t] = a;
    } else {
#pragma unroll
        for (int d = 0; d < 3; d++) {
            int q = min(max(t + 2 * (d - 1), 0), 255);
            float ax = 0.f, ay = 0.f;
#pragma unroll
            for (int o = 0; o < 32; o++) {
                ax += g_PXo[o * 256 + q] * g_PXo[o * 256 + t];
                ay += g_PYo[o * 256 + q] * g_PYo[o * 256 + t];
            }
            g_GX[d * 256 + t] = ax;
            g_GY[d * 256 + t] = ay;
        }
        if (t < 9) {
            int i = t / 3, j = t % 3;
            float a = 0.f;
#pragma unroll
            for (int o = 0; o < 32; o++) a += w_img[o * 3 + i] * w_img[o * 3 + j];
            g_M[t] = a;
        }
    }
}

// ---------------------------------------------------------------------------
// K3: phi kernel — one thread per pixel, 9-neighbor loop (amortized center).
//   g_S already holds sigmoid.  OOB neighbors: finite garbage, killed by
//   agg's zero inp-halo.
// ---------------------------------------------------------------------------
__global__ __launch_bounds__(256) void phi_kernel() {
    int idx = blockIdx.x * 256 + threadIdx.x;   // 0..131071
    int b = idx >> 16;
    int h = (idx >> 8) & 255;
    int w = idx & 255;

    const float* Rb = g_R + ((b * 3) << 16);
    const float* Sb = g_S + (b << 16);
    const int ctr = (h << 8) + w;

    float r0 = __ldg(&Rb[ctr]);
    float r1 = __ldg(&Rb[65536 + ctr]);
    float r2 = __ldg(&Rb[131072 + ctr]);
    float mc0 = __ldg(&g_M[0]) * r0 + __ldg(&g_M[1]) * r1 + __ldg(&g_M[2]) * r2;
    float mc1 = __ldg(&g_M[3]) * r0 + __ldg(&g_M[4]) * r1 + __ldg(&g_M[5]) * r2;
    float mc2 = __ldg(&g_M[6]) * r0 + __ldg(&g_M[7]) * r1 + __ldg(&g_M[8]) * r2;

#pragma unroll
    for (int k = 0; k < 9; k++) {
        int di = (k / 3), dj = (k % 3);
        int hn = min(max(h + 2 * di - 2, 0), 255);
        int wn = min(max(w + 2 * dj - 2, 0), 255);
        int nb = (hn << 8) + wn;
        float fs = __ldg(&Rb[nb]) * mc0 + __ldg(&Rb[65536 + nb]) * mc1
                 + __ldg(&Rb[131072 + nb]) * mc2;
        fs += __ldg(&g_GX[dj * 256 + w]) + __ldg(&g_GY[di * 256 + h]);
        fs += __ldg(&g_T1t[(h << 8) + wn]) + __ldg(&g_T1t[(hn << 8) + w]);
        g_phi[(((b * 9 + k) << 16)) + ctr] = fs * __ldg(&Sb[nb]);
    }
}

// ---------------------------------------------------------------------------
// K4: aggregation.  R5 shape (28x8 tile, smem 32x12, 16 ch, grid 10x32x8,
//   register-buffered loads, one barrier) + CHANNEL-PAIR float2 smem:
//   72 LDS.64 instead of 144 LDS.32 per thread.
// ---------------------------------------------------------------------------
constexpr int TW = 28, TH = 8;
constexpr int SW = 32, SH = 12;
constexpr int CCH = 16;
constexpr int NP = CCH / 2;     // 8 channel pairs

__global__ __launch_bounds__(256) void agg_kernel(
    const float* __restrict__ inp, float* __restrict__ out)
{
    const int z  = blockIdx.z;
    const int b  = z >> 2;
    const int ch0 = (z & 3) * CCH;
    const int h0 = blockIdx.y * TH;
    const int w0 = blockIdx.x * TW;
    const int tid = threadIdx.x;
    const int tx = tid & 31;
    const int ty = tid >> 5;      // 0..7

    __shared__ float2 sT[NP][SH][SW];   // 24.6 KB

    const int gw = w0 - 2 + tx;
    const bool vw = (unsigned)gw < (unsigned)PW;
    const int gh0 = h0 - 2 + ty;
    const int gh1 = gh0 + 8;
    const bool vh0 = (unsigned)gh0 < (unsigned)PH;
    const bool vh1 = (unsigned)gh1 < (unsigned)PH;

    const bool active = (tx < TW) && (w0 + tx < PW);
    const int h = h0 + ty, w = w0 + tx;
    const int ctr = (h << 8) + w;

    // ---- issue all global loads up front ----
    float v0[CCH], v1[CCH];
    const int ibase = ((b * PC + ch0) << 16);
#pragma unroll
    for (int c = 0; c < CCH; c++) {
        int cofs = ibase + (c << 16);
        v0[c] = (vw && vh0) ? __ldg(&inp[cofs + (gh0 << 8) + gw]) : 0.f;
        if (ty < 4)
            v1[c] = (vw && vh1) ? __ldg(&inp[cofs + (gh1 << 8) + gw]) : 0.f;
    }
    float phi[9];
    if (active) {
        const float* pb = g_phi + ((b * 9) << 16) + ctr;
#pragma unroll
        for (int k = 0; k < 9; k++) phi[k] = __ldg(&pb[k << 16]);
    }

    // ---- stage to smem as channel pairs (STS.64) ----
#pragma unroll
    for (int p = 0; p < NP; p++) {
        sT[p][ty][tx] = make_float2(v0[2 * p], v0[2 * p + 1]);
        if (ty < 4)
            sT[p][ty + 8][tx] = make_float2(v1[2 * p], v1[2 * p + 1]);
    }
    __syncthreads();

    // ---- compute: 9 LDS.64 per pair ----
    if (active) {
        const int obase = ((b * PC + ch0) << 16) + ctr;
#pragma unroll
        for (int p = 0; p < NP; p++) {
            float a0 = 0.f, a1 = 0.f;
#pragma unroll
            for (int k = 0; k < 9; k++) {
                float2 v = sT[p][ty + 2 * (k / 3)][tx + 2 * (k % 3)];
                a0 += phi[k] * v.x;
                a1 += phi[k] * v.y;
            }
            out[obase + ((2 * p) << 16)]     = a0;
            out[obase + ((2 * p + 1) << 16)] = a1;
        }
    }
}

// ---------------------------------------------------------------------------
extern "C" void kernel_launch(void* const* d_in, const int* in_sizes, int n_in,
                              void* d_out, int out_size)
{
    const float* inp    = (const float*)d_in[0];   // [2,64,256,256]
    const float* img    = (const float*)d_in[1];   // [2,3,512,512]
    const float* w_pos  = (const float*)d_in[2];   // [32,64]
    const float* w_img  = (const float*)d_in[3];   // [32,3]
    const float* w_comp = (const float*)d_in[4];   // [64]
    float* out = (float*)d_out;

    prep_kernel<<<2112, 256>>>(inp, img, w_pos, w_comp);
    tables_kernel<<<257, 256>>>(w_img);
    phi_kernel<<<512, 256>>>();
    dim3 grid((PW + TW - 1) / TW, PH / TH, PB * 4);   // 10 x 32 x 8 = 2560
    agg_kernel<<<grid, 256>>>(inp, out);
}

// round 10
// speedup vs baseline: 1.5849x; 1.1019x over previous
#include <cuda_runtime.h>

constexpr int PB = 2, PC = 64, PH = 256, PW = 256, IMG = 512;

// Scratch (device globals)
__device__ float g_R[PB * 3 * PH * PW];   // resized img (3 ch)
__device__ float g_S[PB * PH * PW];       // sigmoid(inp . w_comp)
__device__ float g_PXo[32 * PW];          // pos basis [o][w]
__device__ float g_PYo[32 * PH];
__device__ float g_T1t[PH * PW];          // T1t[h][w] = sum_o PX[o,w]*PY[o,h]
__device__ float g_GX[3 * PW];            // GX[d][w]
__device__ float g_GY[3 * PH];
__device__ float g_M[9];                  // w_img^T w_img
__device__ float g_phi[PB * 9 * PH * PW]; // per-neighbor weight, 4.7 MB

// ---------------------------------------------------------------------------
// K1: prep = pos basis (0..63) + sigmoid(S) (64..575) + resize (576..2111)
// ---------------------------------------------------------------------------
__device__ __forceinline__ void make_taps(int o, int* j, float* wt) {
    j[0] = 2 * o - 1; j[1] = 2 * o; j[2] = 2 * o + 1; j[3] = 2 * o + 2;
    wt[0] = 0.125f; wt[1] = 0.375f; wt[2] = 0.375f; wt[3] = 0.125f;
    if (o == 0) {
        j[0] = 0; wt[0] = 0.f;
        wt[1] = 3.f / 7.f; wt[2] = 3.f / 7.f; wt[3] = 1.f / 7.f;
    } else if (o == 255) {
        j[3] = 511; wt[3] = 0.f;
        wt[0] = 1.f / 7.f; wt[1] = 3.f / 7.f; wt[2] = 3.f / 7.f;
    }
}

__global__ __launch_bounds__(256) void prep_kernel(
    const float* __restrict__ inp, const float* __restrict__ img,
    const float* __restrict__ wp, const float* __restrict__ w_comp)
{
    int bx = blockIdx.x;
    if (bx < 64) {
        int o = bx >> 1;
        int half = bx & 1;
        int p = threadIdx.x;
        const float kexp = -0.28782313662425575f;  // -ln(10000)/32
        float acc = 0.f;
        int cbase = half ? 32 : 0;
#pragma unroll
        for (int i = 0; i < 16; i++) {
            float dv = __expf((float)(2 * i) * kexp);
            float s, c;
            __sincosf((float)p * dv, &s, &c);
            acc += wp[o * 64 + cbase + 2 * i] * s + wp[o * 64 + cbase + 2 * i + 1] * c;
        }
        if (half == 0) g_PXo[o * 256 + p] = acc;
        else           g_PYo[o * 256 + p] = acc;
    } else if (bx < 576) {
        int idx = (bx - 64) * 256 + threadIdx.x;
        int b = idx >> 16;
        int pix = idx & 65535;
        const float* ip = inp + ((b * PC) << 16) + pix;
        float acc = 0.f;
#pragma unroll
        for (int c = 0; c < PC; c++)
            acc += __ldg(&w_comp[c]) * __ldg(&ip[c << 16]);
        g_S[(b << 16) + pix] = 1.f / (1.f + __expf(-acc));
    } else {
        int bb = bx - 576;
        int h = bb & 255;
        int bc = bb >> 8;
        int w = threadIdx.x;
        int jh[4], jw[4]; float wh[4], ww[4];
        make_taps(h, jh, wh);
        make_taps(w, jw, ww);
        const float* ip = img + bc * IMG * IMG;
        float acc = 0.f;
#pragma unroll
        for (int a = 0; a < 4; a++) {
            float row = 0.f;
#pragma unroll
            for (int t = 0; t < 4; t++) row += ww[t] * __ldg(&ip[jh[a] * IMG + jw[t]]);
            acc += wh[a] * row;
        }
        g_R[(bc * 256 + h) * 256 + w] = acc;
    }
}

// ---------------------------------------------------------------------------
// K2: gram tables
// ---------------------------------------------------------------------------
__global__ void tables_kernel(const float* __restrict__ w_img) {
    int bx = blockIdx.x, t = threadIdx.x;
    if (bx < 256) {
        __shared__ float sPY[32];
        if (t < 32) sPY[t] = g_PYo[t * 256 + bx];
        __syncthreads();
        float a = 0.f;
#pragma unroll
        for (int o = 0; o < 32; o++) a += sPY[o] * g_PXo[o * 256 + t];
        g_T1t[bx * 256 + t] = a;
    } else {
#pragma unroll
        for (int d = 0; d < 3; d++) {
            int q = min(max(t + 2 * (d - 1), 0), 255);
            float ax = 0.f, ay = 0.f;
#pragma unroll
            for (int o = 0; o < 32; o++) {
                ax += g_PXo[o * 256 + q] * g_PXo[o * 256 + t];
                ay += g_PYo[o * 256 + q] * g_PYo[o * 256 + t];
            }
            g_GX[d * 256 + t] = ax;
            g_GY[d * 256 + t] = ay;
        }
        if (t < 9) {
            int i = t / 3, j = t % 3;
            float a = 0.f;
#pragma unroll
            for (int o = 0; o < 32; o++) a += w_img[o * 3 + i] * w_img[o * 3 + j];
            g_M[t] = a;
        }
    }
}

// ---------------------------------------------------------------------------
// K3: phi kernel — one thread per pixel, 9-neighbor loop.
// ---------------------------------------------------------------------------
__global__ __launch_bounds__(256) void phi_kernel() {
    int idx = blockIdx.x * 256 + threadIdx.x;   // 0..131071
    int b = idx >> 16;
    int h = (idx >> 8) & 255;
    int w = idx & 255;

    const float* Rb = g_R + ((b * 3) << 16);
    const float* Sb = g_S + (b << 16);
    const int ctr = (h << 8) + w;

    float r0 = __ldg(&Rb[ctr]);
    float r1 = __ldg(&Rb[65536 + ctr]);
    float r2 = __ldg(&Rb[131072 + ctr]);
    float mc0 = __ldg(&g_M[0]) * r0 + __ldg(&g_M[1]) * r1 + __ldg(&g_M[2]) * r2;
    float mc1 = __ldg(&g_M[3]) * r0 + __ldg(&g_M[4]) * r1 + __ldg(&g_M[5]) * r2;
    float mc2 = __ldg(&g_M[6]) * r0 + __ldg(&g_M[7]) * r1 + __ldg(&g_M[8]) * r2;

#pragma unroll
    for (int k = 0; k < 9; k++) {
        int di = (k / 3), dj = (k % 3);
        int hn = min(max(h + 2 * di - 2, 0), 255);
        int wn = min(max(w + 2 * dj - 2, 0), 255);
        int nb = (hn << 8) + wn;
        float fs = __ldg(&Rb[nb]) * mc0 + __ldg(&Rb[65536 + nb]) * mc1
                 + __ldg(&Rb[131072 + nb]) * mc2;
        fs += __ldg(&g_GX[dj * 256 + w]) + __ldg(&g_GY[di * 256 + h]);
        fs += __ldg(&g_T1t[(h << 8) + wn]) + __ldg(&g_T1t[(hn << 8) + w]);
        g_phi[(((b * 9 + k) << 16)) + ctr] = fs * __ldg(&Sb[nb]);
    }
}

// ---------------------------------------------------------------------------
// K4: aggregation with stride-2 row-pair register blocking.
//   Block: 28(w) x 16(h) x 8(ch).  smem float2 sT[4][20][32] = 20 KB.
//   ty -> row pair {(0,2),(1,3),(4,6),(5,7),(8,10),(9,11),(12,14),(13,15)}:
//   r1 = ((ty>>1)<<2)|(ty&1), r2 = r1+2.  Rows r1,r1+2,r1+4 serve out-row r1;
//   r1+2,r1+4,r1+6 serve r2 -> 4 row-reads for 2 outputs (24 B/px/ch).
//   Batched LDGs, ONE __syncthreads.
// ---------------------------------------------------------------------------
constexpr int TW = 28, TH = 16;
constexpr int SW = 32, SH = 20;
constexpr int CCH = 8;
constexpr int NP = CCH / 2;     // 4 channel pairs

__global__ __launch_bounds__(256) void agg_kernel(
    const float* __restrict__ inp, float* __restrict__ out)
{
    const int z  = blockIdx.z;
    const int b  = z >> 3;
    const int ch0 = (z & 7) * CCH;
    const int h0 = blockIdx.y * TH;
    const int w0 = blockIdx.x * TW;
    const int tid = threadIdx.x;
    const int tx = tid & 31;
    const int ty = tid >> 5;      // 0..7

    __shared__ float2 sT[NP][SH][SW];   // 20 KB

    // loader coords: rows ty, ty+8, ty+16 (ty<4) of the 20-row tile
    const int gw = w0 - 2 + tx;
    const bool vw = (unsigned)gw < (unsigned)PW;
    const int ghA = h0 - 2 + ty;
    const int ghB = ghA + 8;
    const int ghC = ghA + 16;
    const bool vhA = (unsigned)ghA < (unsigned)PH;
    const bool vhB = (unsigned)ghB < (unsigned)PH;
    const bool vhC = (unsigned)ghC < (unsigned)PH;

    // ---- issue all inp loads up front ----
    float vA[CCH], vB[CCH], vC[CCH];
    const int ibase = ((b * PC + ch0) << 16);
#pragma unroll
    for (int c = 0; c < CCH; c++) {
        const int cofs = ibase + (c << 16);
        vA[c] = (vw && vhA) ? __ldg(&inp[cofs + (ghA << 8) + gw]) : 0.f;
        vB[c] = (vw && vhB) ? __ldg(&inp[cofs + (ghB << 8) + gw]) : 0.f;
        if (ty < 4)
            vC[c] = (vw && vhC) ? __ldg(&inp[cofs + (ghC << 8) + gw]) : 0.f;
    }

    // compute coords: stride-2 row pair
    const int r1 = ((ty >> 1) << 2) | (ty & 1);   // 0,1,4,5,8,9,12,13
    const int h1 = h0 + r1;                        // out rows h1, h1+2
    const int w = w0 + tx;
    const bool active = (tx < TW) && (w < PW);

    // ---- phi loads for both rows ----
    float phA[9], phB[9];
    if (active) {
        const float* pb = g_phi + ((b * 9) << 16) + (h1 << 8) + w;
#pragma unroll
        for (int k = 0; k < 9; k++) {
            phA[k] = __ldg(&pb[k << 16]);
            phB[k] = __ldg(&pb[(k << 16) + 512]);   // row h1+2
        }
    }

    // ---- stage to smem (STS.64 channel pairs) ----
#pragma unroll
    for (int p = 0; p < NP; p++) {
        sT[p][ty][tx]      = make_float2(vA[2 * p], vA[2 * p + 1]);
        sT[p][ty + 8][tx]  = make_float2(vB[2 * p], vB[2 * p + 1]);
        if (ty < 4)
            sT[p][ty + 16][tx] = make_float2(vC[2 * p], vC[2 * p + 1]);
    }
    __syncthreads();

    // ---- compute: 12 LDS.64 per channel pair for 2x2ch outputs ----
    if (active) {
        const int obase1 = ((b * PC + ch0) << 16) + (h1 << 8) + w;
        const int obase2 = obase1 + 512;            // row h1+2
#pragma unroll
        for (int p = 0; p < NP; p++) {
            float a1x = 0.f, a1y = 0.f, a2x = 0.f, a2y = 0.f;
#pragma unroll
            for (int dj = 0; dj < 3; dj++) {
                const int cc = tx + 2 * dj;
                float2 A = sT[p][r1][cc];
                float2 Bv = sT[p][r1 + 2][cc];
                float2 Cv = sT[p][r1 + 4][cc];
                float2 D = sT[p][r1 + 6][cc];
                a1x += phA[dj] * A.x  + phA[3 + dj] * Bv.x + phA[6 + dj] * Cv.x;
                a1y += phA[dj] * A.y  + phA[3 + dj] * Bv.y + phA[6 + dj] * Cv.y;
                a2x += phB[dj] * Bv.x + phB[3 + dj] * Cv.x + phB[6 + dj] * D.x;
                a2y += phB[dj] * Bv.y + phB[3 + dj] * Cv.y + phB[6 + dj] * D.y;
            }
            out[obase1 + ((2 * p) << 16)]     = a1x;
            out[obase1 + ((2 * p + 1) << 16)] = a1y;
            out[obase2 + ((2 * p) << 16)]     = a2x;
            out[obase2 + ((2 * p + 1) << 16)] = a2y;
        }
    }
}

// ---------------------------------------------------------------------------
extern "C" void kernel_launch(void* const* d_in, const int* in_sizes, int n_in,
                              void* d_out, int out_size)
{
    const float* inp    = (const float*)d_in[0];   // [2,64,256,256]
    const float* img    = (const float*)d_in[1];   // [2,3,512,512]
    const float* w_pos  = (const float*)d_in[2];   // [32,64]
    const float* w_img  = (const float*)d_in[3];   // [32,3]
    const float* w_comp = (const float*)d_in[4];   // [64]
    float* out = (float*)d_out;

    prep_kernel<<<2112, 256>>>(inp, img, w_pos, w_comp);
    tables_kernel<<<257, 256>>>(w_img);
    phi_kernel<<<512, 256>>>();
    dim3 grid((PW + TW - 1) / TW, PH / TH, PB * 8);   // 10 x 16 x 16 = 2560
    agg_kernel<<<grid, 256>>>(inp, out);
}

// round 11
// speedup vs baseline: 1.6279x; 1.0271x over previous
#include <cuda_runtime.h>

constexpr int PB = 2, PC = 64, PH = 256, PW = 256, IMG = 512;

// Scratch (device globals)
__device__ float g_R[PB * 3 * PH * PW];   // resized img (3 ch)
__device__ float g_S[PB * PH * PW];       // sigmoid(inp . w_comp)
__device__ float g_PXo[32 * PW];          // pos basis [o][w]
__device__ float g_PYo[32 * PH];
__device__ float g_T1t[PH * PW];          // T1t[h][w] = sum_o PX[o,w]*PY[o,h]
__device__ float g_GX[3 * PW];
__device__ float g_GY[3 * PH];
__device__ float g_M[9];                  // w_img^T w_img
__device__ float g_phi[PB * 9 * PH * PW]; // per-neighbor weight, 4.7 MB

// ---------------------------------------------------------------------------
// K1: prep = pos basis (0..63) + sigmoid(S) (64..575) + resize (576..2111)
// ---------------------------------------------------------------------------
__device__ __forceinline__ void make_taps(int o, int* j, float* wt) {
    j[0] = 2 * o - 1; j[1] = 2 * o; j[2] = 2 * o + 1; j[3] = 2 * o + 2;
    wt[0] = 0.125f; wt[1] = 0.375f; wt[2] = 0.375f; wt[3] = 0.125f;
    if (o == 0) {
        j[0] = 0; wt[0] = 0.f;
        wt[1] = 3.f / 7.f; wt[2] = 3.f / 7.f; wt[3] = 1.f / 7.f;
    } else if (o == 255) {
        j[3] = 511; wt[3] = 0.f;
        wt[0] = 1.f / 7.f; wt[1] = 3.f / 7.f; wt[2] = 3.f / 7.f;
    }
}

__global__ __launch_bounds__(256) void prep_kernel(
    const float* __restrict__ inp, const float* __restrict__ img,
    const float* __restrict__ wp, const float* __restrict__ w_comp)
{
    int bx = blockIdx.x;
    if (bx < 64) {
        int o = bx >> 1;
        int half = bx & 1;
        int p = threadIdx.x;
        const float kexp = -0.28782313662425575f;  // -ln(10000)/32
        float acc = 0.f;
        int cbase = half ? 32 : 0;
#pragma unroll
        for (int i = 0; i < 16; i++) {
            float dv = __expf((float)(2 * i) * kexp);
            float s, c;
            __sincosf((float)p * dv, &s, &c);
            acc += wp[o * 64 + cbase + 2 * i] * s + wp[o * 64 + cbase + 2 * i + 1] * c;
        }
        if (half == 0) g_PXo[o * 256 + p] = acc;
        else           g_PYo[o * 256 + p] = acc;
    } else if (bx < 576) {
        int idx = (bx - 64) * 256 + threadIdx.x;
        int b = idx >> 16;
        int pix = idx & 65535;
        const float* ip = inp + ((b * PC) << 16) + pix;
        float acc = 0.f;
#pragma unroll
        for (int c = 0; c < PC; c++)
            acc += __ldg(&w_comp[c]) * __ldg(&ip[c << 16]);
        g_S[(b << 16) + pix] = 1.f / (1.f + __expf(-acc));
    } else {
        int bb = bx - 576;
        int h = bb & 255;
        int bc = bb >> 8;
        int w = threadIdx.x;
        int jh[4], jw[4]; float wh[4], ww[4];
        make_taps(h, jh, wh);
        make_taps(w, jw, ww);
        const float* ip = img + bc * IMG * IMG;
        float acc = 0.f;
#pragma unroll
        for (int a = 0; a < 4; a++) {
            float row = 0.f;
#pragma unroll
            for (int t = 0; t < 4; t++) row += ww[t] * __ldg(&ip[jh[a] * IMG + jw[t]]);
            acc += wh[a] * row;
        }
        g_R[(bc * 256 + h) * 256 + w] = acc;
    }
}

// ---------------------------------------------------------------------------
// K2: gram tables
// ---------------------------------------------------------------------------
__global__ void tables_kernel(const float* __restrict__ w_img) {
    int bx = blockIdx.x, t = threadIdx.x;
    if (bx < 256) {
        __shared__ float sPY[32];
        if (t < 32) sPY[t] = g_PYo[t * 256 + bx];
        __syncthreads();
        float a = 0.f;
#pragma unroll
        for (int o = 0; o < 32; o++) a += sPY[o] * g_PXo[o * 256 + t];
        g_T1t[bx * 256 + t] = a;
    } else {
#pragma unroll
        for (int d = 0; d < 3; d++) {
            int q = min(max(t + 2 * (d - 1), 0), 255);
            float ax = 0.f, ay = 0.f;
#pragma unroll
            for (int o = 0; o < 32; o++) {
                ax += g_PXo[o * 256 + q] * g_PXo[o * 256 + t];
                ay += g_PYo[o * 256 + q] * g_PYo[o * 256 + t];
            }
            g_GX[d * 256 + t] = ax;
            g_GY[d * 256 + t] = ay;
        }
        if (t < 9) {
            int i = t / 3, j = t % 3;
            float a = 0.f;
#pragma unroll
            for (int o = 0; o < 32; o++) a += w_img[o * 3 + i] * w_img[o * 3 + j];
            g_M[t] = a;
        }
    }
}

// ---------------------------------------------------------------------------
// K3: phi kernel — one thread per pixel, 9-neighbor loop.
// ---------------------------------------------------------------------------
__global__ __launch_bounds__(256) void phi_kernel() {
    int idx = blockIdx.x * 256 + threadIdx.x;   // 0..131071
    int b = idx >> 16;
    int h = (idx >> 8) & 255;
    int w = idx & 255;

    const float* Rb = g_R + ((b * 3) << 16);
    const float* Sb = g_S + (b << 16);
    const int ctr = (h << 8) + w;

    float r0 = __ldg(&Rb[ctr]);
    float r1 = __ldg(&Rb[65536 + ctr]);
    float r2 = __ldg(&Rb[131072 + ctr]);
    float mc0 = __ldg(&g_M[0]) * r0 + __ldg(&g_M[1]) * r1 + __ldg(&g_M[2]) * r2;
    float mc1 = __ldg(&g_M[3]) * r0 + __ldg(&g_M[4]) * r1 + __ldg(&g_M[5]) * r2;
    float mc2 = __ldg(&g_M[6]) * r0 + __ldg(&g_M[7]) * r1 + __ldg(&g_M[8]) * r2;

#pragma unroll
    for (int k = 0; k < 9; k++) {
        int di = (k / 3), dj = (k % 3);
        int hn = min(max(h + 2 * di - 2, 0), 255);
        int wn = min(max(w + 2 * dj - 2, 0), 255);
        int nb = (hn << 8) + wn;
        float fs = __ldg(&Rb[nb]) * mc0 + __ldg(&Rb[65536 + nb]) * mc1
                 + __ldg(&Rb[131072 + nb]) * mc2;
        fs += __ldg(&g_GX[dj * 256 + w]) + __ldg(&g_GY[di * 256 + h]);
        fs += __ldg(&g_T1t[(h << 8) + wn]) + __ldg(&g_T1t[(hn << 8) + w]);
        g_phi[(((b * 9 + k) << 16)) + ctr] = fs * __ldg(&Sb[nb]);
    }
}

// ---------------------------------------------------------------------------
// K4: aggregation, stride-2 row QUAD blocking + float4 channel quads.
//   Block: 28(w) x 32(h) x 4(ch).  smem float4 sT[36][32] = 18.4 KB.
//   Thread ty -> base row r1 = ((ty>>1)<<3)|(ty&1); outputs r1+{0,2,4,6}.
//   Tap rows r1+2j (j=0..5): 6 row-reads serve 4 outputs (1.5 rows/out).
//   18 LDS.128 per thread -> 16 outputs.  Batched LDGs, ONE barrier.
// ---------------------------------------------------------------------------
constexpr int TW = 28, TH = 32;
constexpr int SW = 32, SH = 36;
constexpr int CCH = 4;

__global__ __launch_bounds__(256) void agg_kernel(
    const float* __restrict__ inp, float* __restrict__ out)
{
    const int z  = blockIdx.z;
    const int b  = z >> 4;
    const int ch0 = (z & 15) * CCH;
    const int h0 = blockIdx.y * TH;
    const int w0 = blockIdx.x * TW;
    const int tid = threadIdx.x;
    const int tx = tid & 31;
    const int ty = tid >> 5;      // 0..7

    __shared__ float4 sT[SH][SW];   // 18.4 KB

    // loader: rows ty, ty+8, ty+16, ty+24, and (ty<4) ty+32
    const int gw = w0 - 2 + tx;
    const bool vw = (unsigned)gw < (unsigned)PW;
    const int ibase = ((b * PC + ch0) << 16);

    float4 vr[5];
#pragma unroll
    for (int r = 0; r < 5; r++) {
        const int srow = ty + 8 * r;
        if (r < 4 || ty < 4) {
            const int gh = h0 - 2 + srow;
            const bool v = vw && ((unsigned)gh < (unsigned)PH);
            const int pofs = (gh << 8) + gw;
            vr[r].x = v ? __ldg(&inp[ibase + pofs]) : 0.f;
            vr[r].y = v ? __ldg(&inp[ibase + 65536 + pofs]) : 0.f;
            vr[r].z = v ? __ldg(&inp[ibase + 131072 + pofs]) : 0.f;
            vr[r].w = v ? __ldg(&inp[ibase + 196608 + pofs]) : 0.f;
        }
    }

    // compute coords: stride-2 row quad
    const int r1 = ((ty >> 1) << 3) | (ty & 1);   // 0,1,8,9,16,17,24,25
    const int w = w0 + tx;
    const bool active = (tx < TW) && (w < PW);

    // ---- phi loads: 4 output rows x 9 ----
    float ph[4][9];
    if (active) {
        const float* pb = g_phi + ((b * 9) << 16) + ((h0 + r1) << 8) + w;
#pragma unroll
        for (int i = 0; i < 4; i++)
#pragma unroll
            for (int k = 0; k < 9; k++)
                ph[i][k] = __ldg(&pb[(k << 16) + (i << 9)]);
    }

    // ---- stage to smem ----
#pragma unroll
    for (int r = 0; r < 5; r++) {
        if (r < 4) sT[ty + 8 * r][tx] = vr[r];
        else if (ty < 4) sT[ty + 32][tx] = vr[4];
    }
    __syncthreads();

    // ---- compute: 6 tap rows x 3 cols LDS.128; out i uses taps j=i..i+2 ----
    if (active) {
        float4 acc[4];
#pragma unroll
        for (int i = 0; i < 4; i++) acc[i] = make_float4(0.f, 0.f, 0.f, 0.f);
#pragma unroll
        for (int j = 0; j < 6; j++) {
            const int srow = r1 + 2 * j;
            float4 t0 = sT[srow][tx];
            float4 t1 = sT[srow][tx + 2];
            float4 t2 = sT[srow][tx + 4];
#pragma unroll
            for (int i = 0; i < 4; i++) {
                if (j >= i && j <= i + 2) {
                    const int di = j - i;
                    const float p0 = ph[i][3 * di], p1 = ph[i][3 * di + 1], p2 = ph[i][3 * di + 2];
                    acc[i].x += p0 * t0.x + p1 * t1.x + p2 * t2.x;
                    acc[i].y += p0 * t0.y + p1 * t1.y + p2 * t2.y;
                    acc[i].z += p0 * t0.z + p1 * t1.z + p2 * t2.z;
                    acc[i].w += p0 * t0.w + p1 * t1.w + p2 * t2.w;
                }
            }
        }
        const int obase = ibase + ((h0 + r1) << 8) + w;
#pragma unroll
        for (int i = 0; i < 4; i++) {
            const int ro = obase + (i << 9);
            out[ro]          = acc[i].x;
            out[ro + 65536]  = acc[i].y;
            out[ro + 131072] = acc[i].z;
            out[ro + 196608] = acc[i].w;
        }
    }
}

// ---------------------------------------------------------------------------
extern "C" void kernel_launch(void* const* d_in, const int* in_sizes, int n_in,
                              void* d_out, int out_size)
{
    const float* inp    = (const float*)d_in[0];   // [2,64,256,256]
    const float* img    = (const float*)d_in[1];   // [2,3,512,512]
    const float* w_pos  = (const float*)d_in[2];   // [32,64]
    const float* w_img  = (const float*)d_in[3];   // [32,3]
    const float* w_comp = (const float*)d_in[4];   // [64]
    float* out = (float*)d_out;

    prep_kernel<<<2112, 256>>>(inp, img, w_pos, w_comp);
    tables_kernel<<<257, 256>>>(w_img);
    phi_kernel<<<512, 256>>>();
    dim3 grid((PW + TW - 1) / TW, PH / TH, PB * 16);   // 10 x 8 x 32 = 2560
    agg_kernel<<<grid, 256>>>(inp, out);
}